// round 12
// baseline (speedup 1.0000x reference)
#include <cuda_runtime.h>

// f (32,512,512) f32, K (5,5,512,512) f32, dt (32,) -> out = relu(f + dt * conv_unshared5x5(f, K))
#define BATCH 32
#define H 512
#define W 512
#define HW (H * W)
#define HALO 2

// R4 compute structure (tile 32x8, 128 threads, VY=2, batch-float4, K taps in
// registers once per tile, 2 stages x 16 batches) + persistent CTAs draining
// 1024 tiles via an atomic counter (kills the 1.38-wave quantization tail).
#define TILE_X 32
#define TILE_Y 8
#define SM_ROWS 12
#define SM_COLS 36
#define NPOS (SM_ROWS * SM_COLS)     // 432
#define GSTAGE 4                     // 4 groups of 4 batches per stage
#define TILES_X (W / TILE_X)         // 16
#define NTILES (TILES_X * (H / TILE_Y))  // 1024
#define GRID 740                     // 148 SMs x 5 CTAs

__device__ int g_tile_counter;

#define FMA4(acc, fv, kk)              \
    acc.x = fmaf(fv.x, kk, acc.x);     \
    acc.y = fmaf(fv.y, kk, acc.y);     \
    acc.z = fmaf(fv.z, kk, acc.z);     \
    acc.w = fmaf(fv.w, kk, acc.w);

__global__ __launch_bounds__(128, 5) void op2d_kernel(
    const float* __restrict__ f,
    const float* __restrict__ Kk,
    const float* __restrict__ dt,
    float* __restrict__ out)
{
    __shared__ float4 fs[GSTAGE][SM_ROWS][SM_COLS];   // 27648 B
    __shared__ __align__(16) float dts[BATCH];
    __shared__ int s_tile;

    const int tid = threadIdx.x;
    const int tx = tid & 31;
    const int ty = tid >> 5;

    if (tid < BATCH) dts[tid] = dt[tid];

    while (true) {
        if (tid == 0) s_tile = atomicAdd(&g_tile_counter, 1);
        __syncthreads();               // broadcast tile; fences previous compute
        const int tile = s_tile;
        if (tile >= NTILES) break;

        const int tileX = (tile & (TILES_X - 1)) * TILE_X;
        const int tileY = (tile >> 4) * TILE_Y;

        const int y0 = tileY + 2 * ty;
        const int x  = tileX + tx;
        const int ry = 2 * ty;

        // 2 x 25 per-pixel kernel taps in registers, loaded ONCE per tile,
        // reused across all 32 batches.
        float k0[25], k1[25];
        #pragma unroll
        for (int t = 0; t < 25; t++) {
            k0[t] = __ldg(&Kk[(t * H + y0)     * W + x]);
            k1[t] = __ldg(&Kk[(t * H + y0 + 1) * W + x]);
        }

        float* outp = out + y0 * W + x;

        #pragma unroll 1
        for (int s = 0; s < 2; s++) {      // 2 stages x 16 batches
            if (s) __syncthreads();         // stage-0 compute done before overwrite

            // ---- Stage 16 batches: coalesced LDG, conflict-free STS.128 ----
            const int b0 = s * 16;
            #pragma unroll
            for (int it = 0; it < 4; it++) {   // ceil(432/128)
                const int p = tid + it * 128;
                if (p < NPOS) {
                    const int r = p / SM_COLS;
                    const int c = p - r * SM_COLS;
                    const int gy = tileY + r - HALO;
                    const int gx = tileX + c - HALO;
                    const bool in = ((unsigned)gy < (unsigned)H) & ((unsigned)gx < (unsigned)W);
                    const float* fp = f + (b0 * HW + gy * W + gx);
                    #pragma unroll
                    for (int g = 0; g < GSTAGE; g++) {
                        float4 v;
                        v.x = in ? fp[(g * 4 + 0) * HW] : 0.0f;
                        v.y = in ? fp[(g * 4 + 1) * HW] : 0.0f;
                        v.z = in ? fp[(g * 4 + 2) * HW] : 0.0f;
                        v.w = in ? fp[(g * 4 + 3) * HW] : 0.0f;
                        fs[g][r][c] = v;
                    }
                }
            }
            __syncthreads();

            // ---- Compute: per group, 30 LDS.128 feed 200 FMAs ----
            #pragma unroll
            for (int g = 0; g < GSTAGE; g++) {
                float4 a0 = make_float4(0.f, 0.f, 0.f, 0.f);
                float4 a1 = make_float4(0.f, 0.f, 0.f, 0.f);
                #pragma unroll
                for (int r = 0; r < 6; r++) {
                    float4 fv0 = fs[g][ry + r][tx + 0];
                    float4 fv1 = fs[g][ry + r][tx + 1];
                    float4 fv2 = fs[g][ry + r][tx + 2];
                    float4 fv3 = fs[g][ry + r][tx + 3];
                    float4 fv4 = fs[g][ry + r][tx + 4];
                    if (r < 5) {
                        FMA4(a0, fv0, k0[r * 5 + 0]);
                        FMA4(a0, fv1, k0[r * 5 + 1]);
                        FMA4(a0, fv2, k0[r * 5 + 2]);
                        FMA4(a0, fv3, k0[r * 5 + 3]);
                        FMA4(a0, fv4, k0[r * 5 + 4]);
                    }
                    if (r >= 1) {
                        FMA4(a1, fv0, k1[(r - 1) * 5 + 0]);
                        FMA4(a1, fv1, k1[(r - 1) * 5 + 1]);
                        FMA4(a1, fv2, k1[(r - 1) * 5 + 2]);
                        FMA4(a1, fv3, k1[(r - 1) * 5 + 3]);
                        FMA4(a1, fv4, k1[(r - 1) * 5 + 4]);
                    }
                }
                const int b = b0 + g * 4;
                const float4 dt4 = *(const float4*)&dts[b];
                const float4 fc0 = fs[g][ry + HALO][tx + HALO];
                const float4 fc1 = fs[g][ry + HALO + 1][tx + HALO];

                float* o = outp + b * HW;
                o[0] = fmaxf(fmaf(a0.x, dt4.x, fc0.x), 0.0f);
                o[W] = fmaxf(fmaf(a1.x, dt4.x, fc1.x), 0.0f);
                o += HW;
                o[0] = fmaxf(fmaf(a0.y, dt4.y, fc0.y), 0.0f);
                o[W] = fmaxf(fmaf(a1.y, dt4.y, fc1.y), 0.0f);
                o += HW;
                o[0] = fmaxf(fmaf(a0.z, dt4.z, fc0.z), 0.0f);
                o[W] = fmaxf(fmaf(a1.z, dt4.z, fc1.z), 0.0f);
                o += HW;
                o[0] = fmaxf(fmaf(a0.w, dt4.w, fc0.w), 0.0f);
                o[W] = fmaxf(fmaf(a1.w, dt4.w, fc1.w), 0.0f);
            }
        }
    }
}

extern "C" void kernel_launch(void* const* d_in, const int* in_sizes, int n_in,
                              void* d_out, int out_size)
{
    const float* f  = (const float*)d_in[0];
    const float* Kk = (const float*)d_in[1];
    const float* dt = (const float*)d_in[2];
    float* out = (float*)d_out;

    void* ctr = nullptr;
    cudaGetSymbolAddress(&ctr, g_tile_counter);
    cudaMemsetAsync(ctr, 0, sizeof(int));   // capture-safe counter reset per replay

    op2d_kernel<<<GRID, 128>>>(f, Kk, dt, out);
}

// round 14
// speedup vs baseline: 1.3023x; 1.3023x over previous
#include <cuda_runtime.h>

// f (32,512,512) f32, K (5,5,512,512) f32, dt (32,) -> out = relu(f + dt * conv_unshared5x5(f, K))
#define BATCH 32
#define H 512
#define W 512
#define HW (H * W)
#define HALO 2

// R4 compute economics (tile 32x8, 128 threads, VY=2, batch-float4, 50 K taps in
// registers once per tile) + cp.async double-buffered staging pipeline:
// 4 stages x 8 batches; stage s+1's LDGSTS copies fly while stage s computes.
#define TILE_X 32
#define TILE_Y 8
#define SM_ROWS 12
#define SM_COLS 36
#define NPOS (SM_ROWS * SM_COLS)   // 432
#define NSTAGE 4                   // 4 stages x 8 batches = 32
#define GS 2                       // float4 groups per stage

#define FMA4(acc, fv, kk)              \
    acc.x = fmaf(fv.x, kk, acc.x);     \
    acc.y = fmaf(fv.y, kk, acc.y);     \
    acc.z = fmaf(fv.z, kk, acc.z);     \
    acc.w = fmaf(fv.w, kk, acc.w);

__device__ __forceinline__ unsigned smem_u32(const void* p) {
    return (unsigned)__cvta_generic_to_shared(p);
}
__device__ __forceinline__ void cpasync4(unsigned dst, const float* src, unsigned nbytes) {
    asm volatile("cp.async.ca.shared.global [%0], [%1], 4, %2;\n"
                 :: "r"(dst), "l"(src), "r"(nbytes));
}
#define CP_COMMIT() asm volatile("cp.async.commit_group;\n" ::: "memory")
#define CP_WAIT1()  asm volatile("cp.async.wait_group 1;\n" ::: "memory")
#define CP_WAIT0()  asm volatile("cp.async.wait_group 0;\n" ::: "memory")

__global__ __launch_bounds__(128) void op2d_kernel(
    const float* __restrict__ f,
    const float* __restrict__ Kk,
    const float* __restrict__ dt,
    float* __restrict__ out)
{
    __shared__ float4 fs[2][GS][SM_ROWS][SM_COLS];   // 2 buffers x 8 batches: 27648 B
    __shared__ __align__(16) float dts[BATCH];

    const int tid = threadIdx.x;
    const int tx = tid & 31;
    const int ty = tid >> 5;
    const int tileX = blockIdx.x * TILE_X;
    const int tileY = blockIdx.y * TILE_Y;

    if (tid < BATCH) dts[tid] = dt[tid];

    const int y0 = tileY + 2 * ty;
    const int x  = tileX + tx;
    const int ry = 2 * ty;

    // Per-thread staging geometry (4 chunks of 128 positions).
    int rr[4], cc[4];
    unsigned inmask[4];
    const float* fbase[4];
    #pragma unroll
    for (int it = 0; it < 4; it++) {
        const int p = tid + it * 128;
        const int r = p / SM_COLS;
        const int c = p - r * SM_COLS;
        rr[it] = r; cc[it] = c;
        const int gy = tileY + r - HALO;
        const int gx = tileX + c - HALO;
        const bool in = (p < NPOS) && ((unsigned)gy < (unsigned)H) && ((unsigned)gx < (unsigned)W);
        inmask[it] = in ? 4u : 0u;
        fbase[it]  = in ? (f + gy * W + gx) : f;   // safe pointer when masked
    }

    // Issue stage-0 copies first so they overlap the K-tap loads below.
    {
        #pragma unroll
        for (int it = 0; it < 4; it++) {
            if (tid + it * 128 < NPOS) {
                #pragma unroll
                for (int g = 0; g < GS; g++) {
                    unsigned d = smem_u32(&fs[0][g][rr[it]][cc[it]]);
                    #pragma unroll
                    for (int k = 0; k < 4; k++)
                        cpasync4(d + 4 * k, fbase[it] + (g * 4 + k) * HW, inmask[it]);
                }
            }
        }
        CP_COMMIT();
    }

    // 2 x 25 per-pixel kernel taps in registers (overlap with stage-0 cp.async).
    float k0[25], k1[25];
    #pragma unroll
    for (int t = 0; t < 25; t++) {
        k0[t] = __ldg(&Kk[(t * H + y0)     * W + x]);
        k1[t] = __ldg(&Kk[(t * H + y0 + 1) * W + x]);
    }

    float* outp = out + y0 * W + x;

    #pragma unroll 1
    for (int s = 0; s < NSTAGE; s++) {
        // Issue stage s+1 into the other buffer (freed by stage s-1's compute,
        // which ended with a __syncthreads last iteration).
        if (s + 1 < NSTAGE) {
            const int bb = (s + 1) & 1;
            const int boff = (s + 1) * 8;
            #pragma unroll
            for (int it = 0; it < 4; it++) {
                if (tid + it * 128 < NPOS) {
                    #pragma unroll
                    for (int g = 0; g < GS; g++) {
                        unsigned d = smem_u32(&fs[bb][g][rr[it]][cc[it]]);
                        #pragma unroll
                        for (int k = 0; k < 4; k++)
                            cpasync4(d + 4 * k, fbase[it] + (boff + g * 4 + k) * HW, inmask[it]);
                    }
                }
            }
            CP_COMMIT();
            CP_WAIT1();      // stage s landed; s+1 still in flight
        } else {
            CP_WAIT0();      // last stage: wait for it
        }
        __syncthreads();

        // ---- Compute stage s (8 batches, 2 groups) ----
        const int pb = s & 1;
        const int b0 = s * 8;
        #pragma unroll
        for (int g = 0; g < GS; g++) {
            float4 a0 = make_float4(0.f, 0.f, 0.f, 0.f);
            float4 a1 = make_float4(0.f, 0.f, 0.f, 0.f);
            #pragma unroll
            for (int r = 0; r < 6; r++) {
                float4 fv0 = fs[pb][g][ry + r][tx + 0];
                float4 fv1 = fs[pb][g][ry + r][tx + 1];
                float4 fv2 = fs[pb][g][ry + r][tx + 2];
                float4 fv3 = fs[pb][g][ry + r][tx + 3];
                float4 fv4 = fs[pb][g][ry + r][tx + 4];
                if (r < 5) {
                    FMA4(a0, fv0, k0[r * 5 + 0]);
                    FMA4(a0, fv1, k0[r * 5 + 1]);
                    FMA4(a0, fv2, k0[r * 5 + 2]);
                    FMA4(a0, fv3, k0[r * 5 + 3]);
                    FMA4(a0, fv4, k0[r * 5 + 4]);
                }
                if (r >= 1) {
                    FMA4(a1, fv0, k1[(r - 1) * 5 + 0]);
                    FMA4(a1, fv1, k1[(r - 1) * 5 + 1]);
                    FMA4(a1, fv2, k1[(r - 1) * 5 + 2]);
                    FMA4(a1, fv3, k1[(r - 1) * 5 + 3]);
                    FMA4(a1, fv4, k1[(r - 1) * 5 + 4]);
                }
            }
            const int b = b0 + g * 4;
            const float4 dt4 = *(const float4*)&dts[b];
            const float4 fc0 = fs[pb][g][ry + HALO][tx + HALO];
            const float4 fc1 = fs[pb][g][ry + HALO + 1][tx + HALO];

            float* o = outp + b * HW;
            o[0] = fmaxf(fmaf(a0.x, dt4.x, fc0.x), 0.0f);
            o[W] = fmaxf(fmaf(a1.x, dt4.x, fc1.x), 0.0f);
            o += HW;
            o[0] = fmaxf(fmaf(a0.y, dt4.y, fc0.y), 0.0f);
            o[W] = fmaxf(fmaf(a1.y, dt4.y, fc1.y), 0.0f);
            o += HW;
            o[0] = fmaxf(fmaf(a0.z, dt4.z, fc0.z), 0.0f);
            o[W] = fmaxf(fmaf(a1.z, dt4.z, fc1.z), 0.0f);
            o += HW;
            o[0] = fmaxf(fmaf(a0.w, dt4.w, fc0.w), 0.0f);
            o[W] = fmaxf(fmaf(a1.w, dt4.w, fc1.w), 0.0f);
        }
        __syncthreads();   // all reads of buffer pb done before it is refilled
    }
}

extern "C" void kernel_launch(void* const* d_in, const int* in_sizes, int n_in,
                              void* d_out, int out_size)
{
    const float* f  = (const float*)d_in[0];
    const float* Kk = (const float*)d_in[1];
    const float* dt = (const float*)d_in[2];
    float* out = (float*)d_out;

    dim3 grid(W / TILE_X, H / TILE_Y);  // (16, 64) = 1024 blocks
    dim3 block(128);
    op2d_kernel<<<grid, block>>>(f, Kk, dt, out);
}